// round 1
// baseline (speedup 1.0000x reference)
#include <cuda_runtime.h>
#include <cuda_bf16.h>

#define MMAX 50000
#define HNB 32
#define CIN 128
#define CMID 32
#define KPTS 15
#define CPG 16
#define BNEPS 1e-5f
#define NEG 0.1f
#define FULLM 0xffffffffu

// scratch (device globals; no allocation allowed)
__device__ float g_x1[MMAX * CMID];   // unary1 output (raw, then normalized in place)
__device__ float g_cv[MMAX * CMID];   // conv output (raw)
// stats raw sums: [0:32) sum1 [32:64) sq1 [64:96) sum2 [96:128) sq2 [128:256) sum3 [256:384) sq3
__device__ float g_stats[384];
// finalized: same layout but (mean, invstd) per stage
__device__ float g_bnp[384];

__global__ void zero_stats() {
    if (threadIdx.x < 384) g_stats[threadIdx.x] = 0.f;
}

__global__ void finalize_bn(int off, int n, float invM) {
    int t = threadIdx.x;
    if (t < n) {
        float s = g_stats[off + t], q = g_stats[off + n + t];
        float m = s * invM;
        float v = q * invM - m * m;
        g_bnp[off + t] = m;
        g_bnp[off + n + t] = rsqrtf(v + BNEPS);
    }
}

// ---------- unary1: y1 = s_feats(M,128) @ w_u1(128,32), accumulate batch stats ----------
__global__ __launch_bounds__(256) void k_unary1(const float* __restrict__ sfeat,
                                                const float* __restrict__ w_u1, int M) {
    __shared__ float ws[CIN * CMID];      // 16 KB
    __shared__ float srow[8][CIN];
    __shared__ float red[8][2][CMID];
    for (int i = threadIdx.x; i < CIN * CMID; i += blockDim.x) ws[i] = w_u1[i];
    __syncthreads();
    int warp = threadIdx.x >> 5, lane = threadIdx.x & 31;
    int wgid = blockIdx.x * 8 + warp;
    int nw = gridDim.x * 8;
    float lsum = 0.f, lsq = 0.f;
    for (int m = wgid; m < M; m += nw) {
        const float4* r4 = (const float4*)(sfeat + (size_t)m * CIN);
        ((float4*)srow[warp])[lane] = r4[lane];
        __syncwarp();
        float a0 = 0.f, a1 = 0.f, a2 = 0.f, a3 = 0.f;
        #pragma unroll 16
        for (int i = 0; i < CIN; i += 4) {
            a0 = fmaf(srow[warp][i + 0], ws[(i + 0) * CMID + lane], a0);
            a1 = fmaf(srow[warp][i + 1], ws[(i + 1) * CMID + lane], a1);
            a2 = fmaf(srow[warp][i + 2], ws[(i + 2) * CMID + lane], a2);
            a3 = fmaf(srow[warp][i + 3], ws[(i + 3) * CMID + lane], a3);
        }
        float acc = (a0 + a1) + (a2 + a3);
        g_x1[(size_t)m * CMID + lane] = acc;
        lsum += acc; lsq += acc * acc;
        __syncwarp();
    }
    red[warp][0][lane] = lsum; red[warp][1][lane] = lsq;
    __syncthreads();
    if (warp == 0) {
        float s = 0.f, q = 0.f;
        #pragma unroll
        for (int w = 0; w < 8; w++) { s += red[w][0][lane]; q += red[w][1][lane]; }
        atomicAdd(&g_stats[lane], s);
        atomicAdd(&g_stats[32 + lane], q);
    }
}

// ---------- apply BN1 + LeakyReLU in place on g_x1 ----------
__global__ void k_bn1(const float* __restrict__ g1, const float* __restrict__ b1, int M) {
    int t = blockIdx.x * blockDim.x + threadIdx.x;
    int n = M * CMID;
    if (t < n) {
        int c = t & 31;
        float x = g_x1[t];
        float y = (x - g_bnp[c]) * g_bnp[32 + c] * g1[c] + b1[c];
        g_x1[t] = (y >= 0.f) ? y : NEG * y;
    }
}

// ---------- KPInv conv: one warp per point ----------
__global__ __launch_bounds__(256) void k_conv(const float* __restrict__ q_pts,
                                              const float* __restrict__ s_pts,
                                              const int* __restrict__ nidx,
                                              const float* __restrict__ kp,
                                              const float* __restrict__ w_g1,
                                              const float* __restrict__ b_g1,
                                              const float* __restrict__ w_g2,
                                              const float* __restrict__ b_g2,
                                              int M) {
    __shared__ float kps[KPTS * 3];
    __shared__ float kpn[KPTS];
    __shared__ float wg1t[8 * CMID];    // transposed: [u][c], conflict-free
    __shared__ float bg1s[8];
    __shared__ float wg2s[8 * 30];
    __shared__ float bg2s[30];
    __shared__ float wbuf[8][32];
    __shared__ float red[8][2][CMID];
    int t = threadIdx.x;
    if (t < KPTS * 3) kps[t] = kp[t];
    if (t < KPTS) kpn[t] = kp[t*3]*kp[t*3] + kp[t*3+1]*kp[t*3+1] + kp[t*3+2]*kp[t*3+2];
    for (int i = t; i < 8 * CMID; i += blockDim.x) {
        int u = i >> 5, c = i & 31;
        wg1t[i] = w_g1[c * 8 + u];
    }
    if (t < 8) bg1s[t] = b_g1[t];
    for (int i = t; i < 8 * 30; i += blockDim.x) wg2s[i] = w_g2[i];
    if (t < 30) bg2s[t] = b_g2[t];
    __syncthreads();

    int warp = t >> 5, lane = t & 31;
    int wgid = blockIdx.x * 8 + warp;
    int nw = gridDim.x * 8;
    float lsum = 0.f, lsq = 0.f;

    for (int m = wgid; m < M; m += nw) {
        int j = nidx[(size_t)m * HNB + lane];           // lane = neighbor h
        float qx = q_pts[m*3], qy = q_pts[m*3+1], qz = q_pts[m*3+2];
        float nx = s_pts[j*3]   - qx;
        float ny = s_pts[j*3+1] - qy;
        float nz = s_pts[j*3+2] - qz;
        float n2 = nx*nx + ny*ny + nz*nz;
        float infl[KPTS];
        #pragma unroll
        for (int k = 0; k < KPTS; k++) {
            float dot = nx*kps[k*3] + ny*kps[k*3+1] + nz*kps[k*3+2];
            float d2 = n2 + kpn[k] - 2.f * dot;
            float d = sqrtf(fmaxf(d2, 0.f));
            infl[k] = fmaxf(1.f - d, 0.f);
        }
        // gather neighbor features: lane = channel c now; keep nf[h] in regs
        float nf[HNB];
        float center = -3.4e38f;
        #pragma unroll
        for (int h = 0; h < HNB; h++) {
            int jh = __shfl_sync(FULLM, j, h);
            float v = __ldg(&g_x1[(size_t)jh * CMID + lane]);
            nf[h] = v;
            center = fmaxf(center, v);
        }
        // hidden = lrelu(center @ w_g1 + b_g1) : warp-reduce 8 partials
        float hp[8];
        #pragma unroll
        for (int u = 0; u < 8; u++) hp[u] = center * wg1t[u * 32 + lane];
        #pragma unroll
        for (int off = 16; off >= 1; off >>= 1)
            #pragma unroll
            for (int u = 0; u < 8; u++) hp[u] += __shfl_xor_sync(FULLM, hp[u], off);
        float hid[8];
        #pragma unroll
        for (int u = 0; u < 8; u++) {
            float v = hp[u] + bg1s[u];
            hid[u] = (v >= 0.f) ? v : NEG * v;
        }
        // w[t] = b_g2[t] + hid @ w_g2, t < 30, layout (K,G): w[k][g] at 2k+g
        float wt = 0.f;
        if (lane < 30) {
            wt = bg2s[lane];
            #pragma unroll
            for (int u = 0; u < 8; u++) wt = fmaf(hid[u], wg2s[u * 30 + lane], wt);
        }
        wbuf[warp][lane] = wt;
        __syncwarp();
        // collapse K: a[h][g] = sum_k w[k][g] * infl[h][k]  (lane = h)
        float a0 = 0.f, a1 = 0.f;
        #pragma unroll
        for (int k = 0; k < KPTS; k++) {
            a0 = fmaf(wbuf[warp][2*k],     infl[k], a0);
            a1 = fmaf(wbuf[warp][2*k + 1], infl[k], a1);
        }
        // out[c] = sum_h a[h][g(c)] * nf[h][c]   (lane = c, g(c) = c/16)
        float out = 0.f;
        bool glo = (lane < CPG);
        #pragma unroll
        for (int h = 0; h < HNB; h++) {
            float a0h = __shfl_sync(FULLM, a0, h);
            float a1h = __shfl_sync(FULLM, a1, h);
            out = fmaf(glo ? a0h : a1h, nf[h], out);
        }
        g_cv[(size_t)m * CMID + lane] = out;
        lsum += out; lsq += out * out;
        __syncwarp();
    }
    red[warp][0][lane] = lsum; red[warp][1][lane] = lsq;
    __syncthreads();
    if (warp == 0) {
        float s = 0.f, q = 0.f;
        #pragma unroll
        for (int w = 0; w < 8; w++) { s += red[w][0][lane]; q += red[w][1][lane]; }
        atomicAdd(&g_stats[64 + lane], s);
        atomicAdd(&g_stats[96 + lane], q);
    }
}

// ---------- BN2+lrelu, then x2 @ w_u2(32,128) -> d_out, accumulate stats3 ----------
__global__ __launch_bounds__(256) void k_unary2(const float* __restrict__ w_u2,
                                                const float* __restrict__ gc,
                                                const float* __restrict__ bc,
                                                float* __restrict__ out, int M) {
    __shared__ float ws[CMID * CIN];   // 16 KB
    __shared__ float x2s[2][CMID];
    __shared__ float red[256];
    int t = threadIdx.x;
    for (int i = t; i < CMID * CIN; i += 256) ws[i] = w_u2[i];
    int grp = t >> 7, lt = t & 127;
    float lsum = 0.f, lsq = 0.f;
    __syncthreads();
    for (int base = blockIdx.x * 2; base < M; base += gridDim.x * 2) {
        int m = base + grp;
        bool act = (m < M);
        if (act && lt < CMID) {
            float x = g_cv[(size_t)m * CMID + lt];
            float y = (x - g_bnp[64 + lt]) * g_bnp[96 + lt] * gc[lt] + bc[lt];
            x2s[grp][lt] = (y >= 0.f) ? y : NEG * y;
        }
        __syncthreads();
        if (act) {
            float a0 = 0.f, a1 = 0.f;
            #pragma unroll
            for (int c = 0; c < CMID; c += 2) {
                a0 = fmaf(x2s[grp][c],     ws[c * CIN + lt],       a0);
                a1 = fmaf(x2s[grp][c + 1], ws[(c + 1) * CIN + lt], a1);
            }
            float acc = a0 + a1;
            out[(size_t)m * CIN + lt] = acc;
            lsum += acc; lsq += acc * acc;
        }
        __syncthreads();
    }
    red[t] = lsum; __syncthreads();
    if (t < 128) atomicAdd(&g_stats[128 + lt], red[t] + red[t + 128]);
    __syncthreads();
    red[t] = lsq; __syncthreads();
    if (t < 128) atomicAdd(&g_stats[256 + lt], red[t] + red[t + 128]);
}

// ---------- final: bn3(x3) + s_feats, lrelu ----------
__global__ void k_final(const float* __restrict__ sfeat, const float* __restrict__ g2,
                        const float* __restrict__ b2, float* __restrict__ out, int M) {
    int t = blockIdx.x * blockDim.x + threadIdx.x;
    int n = M * CIN;
    if (t < n) {
        int c = t & 127;
        float x = out[t];
        float y = (x - g_bnp[128 + c]) * g_bnp[256 + c] * g2[c] + b2[c] + sfeat[t];
        out[t] = (y >= 0.f) ? y : NEG * y;
    }
}

extern "C" void kernel_launch(void* const* d_in, const int* in_sizes, int n_in,
                              void* d_out, int out_size) {
    const float* q_pts  = (const float*)d_in[0];
    const float* s_pts  = (const float*)d_in[1];
    const float* sfeat  = (const float*)d_in[2];
    const int*   nidx   = (const int*)  d_in[3];
    const float* kp     = (const float*)d_in[4];
    const float* w_u1   = (const float*)d_in[5];
    const float* g_u1   = (const float*)d_in[6];
    const float* b_u1   = (const float*)d_in[7];
    const float* w_g1   = (const float*)d_in[8];
    const float* b_g1   = (const float*)d_in[9];
    const float* w_g2   = (const float*)d_in[10];
    const float* b_g2   = (const float*)d_in[11];
    const float* g_c    = (const float*)d_in[12];
    const float* b_c    = (const float*)d_in[13];
    const float* w_u2   = (const float*)d_in[14];
    const float* g_u2   = (const float*)d_in[15];
    const float* b_u2   = (const float*)d_in[16];
    float* out = (float*)d_out;

    int M = in_sizes[2] / CIN;
    float invM = 1.0f / (float)M;

    zero_stats<<<1, 384>>>();
    k_unary1<<<592, 256>>>(sfeat, w_u1, M);
    finalize_bn<<<1, 32>>>(0, 32, invM);
    {
        int n = M * CMID;
        k_bn1<<<(n + 255) / 256, 256>>>(g_u1, b_u1, M);
    }
    k_conv<<<592, 256>>>(q_pts, s_pts, nidx, kp, w_g1, b_g1, w_g2, b_g2, M);
    finalize_bn<<<1, 32>>>(64, 32, invM);
    k_unary2<<<592, 256>>>(w_u2, g_c, b_c, out, M);
    finalize_bn<<<1, 128>>>(128, 128, invM);
    {
        int n = M * CIN;
        k_final<<<(n + 255) / 256, 256>>>(sfeat, g_u2, b_u2, out, M);
    }
}

// round 2
// speedup vs baseline: 1.0891x; 1.0891x over previous
#include <cuda_runtime.h>
#include <cuda_bf16.h>

#define MMAX 50000
#define HNB 32
#define CIN 128
#define CMID 32
#define KPTS 15
#define CPG 16
#define BNEPS 1e-5f
#define NEG 0.1f
#define FULLM 0xffffffffu

// scratch (device globals; no allocation allowed)
__device__ float g_x1[MMAX * CMID];   // unary1 output (raw pre-BN)
__device__ float g_cv[MMAX * CMID];   // conv output (raw pre-BN)
// stats raw sums: [0:32) sum1 [32:64) sq1 [64:96) sum2 [96:128) sq2 [128:256) sum3 [256:384) sq3
__device__ float g_stats[384];
// finalized: (scale, shift) per stage, gamma/beta folded in. layout mirrors g_stats.
__device__ float g_bnp[384];

__global__ void zero_stats() {
    if (threadIdx.x < 384) g_stats[threadIdx.x] = 0.f;
}

// sc = invstd*gamma ; sh = beta - mean*sc
__global__ void finalize_bn(int off, int n, float invM,
                            const float* __restrict__ gamma,
                            const float* __restrict__ beta) {
    int t = threadIdx.x;
    if (t < n) {
        float s = g_stats[off + t], q = g_stats[off + n + t];
        float m = s * invM;
        float v = q * invM - m * m;
        float is = rsqrtf(v + BNEPS);
        float sc = is * gamma[t];
        g_bnp[off + t] = sc;
        g_bnp[off + n + t] = beta[t] - m * sc;
    }
}

// ---------- unary1: y1 = s_feats(M,128) @ w_u1(128,32), accumulate batch stats ----------
__global__ __launch_bounds__(256) void k_unary1(const float* __restrict__ sfeat,
                                                const float* __restrict__ w_u1, int M) {
    __shared__ float4 swt[32 * 32];    // [chunk][c] = w[4*chunk .. 4*chunk+3][c], 16 KB
    __shared__ float4 srow[8][32];     // per-warp row staging (128 floats)
    __shared__ float red[8][2][CMID];
    int t = threadIdx.x;
    for (int i = t; i < CIN * CMID; i += 256) {
        int c = i & 31, ii = i >> 5;             // value = w_u1[ii*32+c] = w_u1[i]
        ((float*)&swt[(ii >> 2) * 32 + c])[ii & 3] = w_u1[i];
    }
    __syncthreads();
    int warp = t >> 5, lane = t & 31;
    int wgid = blockIdx.x * 8 + warp;
    int nw = gridDim.x * 8;
    float lsum = 0.f, lsq = 0.f;
    float4 r4 = make_float4(0.f, 0.f, 0.f, 0.f);
    if (wgid < M) r4 = ((const float4*)(sfeat + (size_t)wgid * CIN))[lane];
    for (int m = wgid; m < M; m += nw) {
        srow[warp][lane] = r4;
        __syncwarp();
        int mn = m + nw;
        float4 r4n = make_float4(0.f, 0.f, 0.f, 0.f);
        if (mn < M) r4n = ((const float4*)(sfeat + (size_t)mn * CIN))[lane];
        float a0 = 0.f, a1 = 0.f, a2 = 0.f, a3 = 0.f;
        #pragma unroll
        for (int ch = 0; ch < 32; ch++) {
            float4 x4 = srow[warp][ch];           // broadcast LDS.128
            float4 w4 = swt[ch * 32 + lane];      // conflict-free LDS.128
            a0 = fmaf(x4.x, w4.x, a0);
            a1 = fmaf(x4.y, w4.y, a1);
            a2 = fmaf(x4.z, w4.z, a2);
            a3 = fmaf(x4.w, w4.w, a3);
        }
        float acc = (a0 + a1) + (a2 + a3);
        g_x1[(size_t)m * CMID + lane] = acc;
        lsum += acc; lsq += acc * acc;
        __syncwarp();
        r4 = r4n;
    }
    red[warp][0][lane] = lsum; red[warp][1][lane] = lsq;
    __syncthreads();
    if (warp == 0) {
        float s = 0.f, q = 0.f;
        #pragma unroll
        for (int w = 0; w < 8; w++) { s += red[w][0][lane]; q += red[w][1][lane]; }
        atomicAdd(&g_stats[lane], s);
        atomicAdd(&g_stats[32 + lane], q);
    }
}

// ---------- KPInv conv: one warp per point. BN1+lrelu fused at gather. ----------
__global__ __launch_bounds__(256) void k_conv(const float* __restrict__ q_pts,
                                              const float* __restrict__ s_pts,
                                              const int* __restrict__ nidx,
                                              const float* __restrict__ kp,
                                              const float* __restrict__ w_g1,
                                              const float* __restrict__ b_g1,
                                              const float* __restrict__ w_g2,
                                              const float* __restrict__ b_g2,
                                              int M) {
    __shared__ float kps[KPTS * 3];
    __shared__ float kpn[KPTS];
    __shared__ float wg1t[8 * CMID];    // transposed: [u][c]
    __shared__ float bg1s[8];
    __shared__ float wg2s[8 * 30];
    __shared__ float bg2s[30];
    __shared__ float wbuf[8][32];
    __shared__ float2 abuf[8][32];
    __shared__ float red[8][2][CMID];
    int t = threadIdx.x;
    if (t < KPTS * 3) kps[t] = kp[t];
    if (t < KPTS) kpn[t] = kp[t*3]*kp[t*3] + kp[t*3+1]*kp[t*3+1] + kp[t*3+2]*kp[t*3+2];
    for (int i = t; i < 8 * CMID; i += blockDim.x) {
        int u = i >> 5, c = i & 31;
        wg1t[i] = w_g1[c * 8 + u];
    }
    if (t < 8) bg1s[t] = b_g1[t];
    for (int i = t; i < 8 * 30; i += blockDim.x) wg2s[i] = w_g2[i];
    if (t < 30) bg2s[t] = b_g2[t];
    __syncthreads();

    int warp = t >> 5, lane = t & 31;
    // BN1 fold (channel = lane in gather phase)
    float sc1 = g_bnp[lane], sh1 = g_bnp[32 + lane];
    int wgid = blockIdx.x * 8 + warp;
    int nw = gridDim.x * 8;
    float lsum = 0.f, lsq = 0.f;

    for (int m = wgid; m < M; m += nw) {
        int j = nidx[(size_t)m * HNB + lane];           // lane = neighbor h
        float qx = q_pts[m*3], qy = q_pts[m*3+1], qz = q_pts[m*3+2];
        float nx = s_pts[j*3]   - qx;
        float ny = s_pts[j*3+1] - qy;
        float nz = s_pts[j*3+2] - qz;
        float n2 = nx*nx + ny*ny + nz*nz;
        float infl[KPTS];
        #pragma unroll
        for (int k = 0; k < KPTS; k++) {
            float dot = nx*kps[k*3] + ny*kps[k*3+1] + nz*kps[k*3+2];
            float d2 = n2 + kpn[k] - 2.f * dot;
            float d = sqrtf(fmaxf(d2, 0.f));
            infl[k] = fmaxf(1.f - d, 0.f);
        }
        // gather neighbor features (lane = channel c), BN1 + lrelu fused
        float nf[HNB];
        float center = -3.4e38f;
        #pragma unroll
        for (int h = 0; h < HNB; h++) {
            int jh = __shfl_sync(FULLM, j, h);
            float v = __ldg(&g_x1[(size_t)jh * CMID + lane]);
            v = fmaf(v, sc1, sh1);
            v = fmaxf(v, NEG * v);                // lrelu
            nf[h] = v;
            center = fmaxf(center, v);
        }
        // hidden = lrelu(center @ w_g1 + b_g1) : warp-reduce 8 partials
        float hp[8];
        #pragma unroll
        for (int u = 0; u < 8; u++) hp[u] = center * wg1t[u * 32 + lane];
        #pragma unroll
        for (int off = 16; off >= 1; off >>= 1)
            #pragma unroll
            for (int u = 0; u < 8; u++) hp[u] += __shfl_xor_sync(FULLM, hp[u], off);
        float hid[8];
        #pragma unroll
        for (int u = 0; u < 8; u++) {
            float v = hp[u] + bg1s[u];
            hid[u] = fmaxf(v, NEG * v);
        }
        // w[t] = b_g2[t] + hid @ w_g2, t < 30, layout (K,G): w[k][g] at 2k+g
        float wt = 0.f;
        if (lane < 30) {
            wt = bg2s[lane];
            #pragma unroll
            for (int u = 0; u < 8; u++) wt = fmaf(hid[u], wg2s[u * 30 + lane], wt);
        }
        wbuf[warp][lane] = wt;
        __syncwarp();
        // collapse K: a[h][g] = sum_k w[k][g] * infl[h][k]  (lane = h)
        float a0 = 0.f, a1 = 0.f;
        #pragma unroll
        for (int k = 0; k < KPTS; k++) {
            a0 = fmaf(wbuf[warp][2*k],     infl[k], a0);
            a1 = fmaf(wbuf[warp][2*k + 1], infl[k], a1);
        }
        abuf[warp][lane] = make_float2(a0, a1);
        __syncwarp();
        // out[c] = sum_h a[h][g(c)] * nf[h][c]   (lane = c, g(c) = c/16)
        const float* ab = (const float*)abuf[warp];
        int gsel = (lane >= CPG) ? 1 : 0;
        float out = 0.f;
        #pragma unroll
        for (int h = 0; h < HNB; h++) {
            out = fmaf(ab[2*h + gsel], nf[h], out);
        }
        g_cv[(size_t)m * CMID + lane] = out;
        lsum += out; lsq += out * out;
        __syncwarp();
    }
    red[warp][0][lane] = lsum; red[warp][1][lane] = lsq;
    __syncthreads();
    if (warp == 0) {
        float s = 0.f, q = 0.f;
        #pragma unroll
        for (int w = 0; w < 8; w++) { s += red[w][0][lane]; q += red[w][1][lane]; }
        atomicAdd(&g_stats[64 + lane], s);
        atomicAdd(&g_stats[96 + lane], q);
    }
}

// ---------- BN2+lrelu, then x2 @ w_u2(32,128) -> d_out, accumulate stats3 ----------
__global__ __launch_bounds__(256) void k_unary2(const float* __restrict__ w_u2,
                                                float* __restrict__ out, int M) {
    __shared__ float4 sw2[32 * 32];    // direct float4 view of w_u2 (32 x 128), 16 KB
    __shared__ float4 x2s4[8][8];      // per-warp BN'd row (32 floats)
    __shared__ float4 red4[2][8][32];  // sum / sq partials per warp
    int t = threadIdx.x;
    for (int i = t; i < 1024; i += 256) sw2[i] = ((const float4*)w_u2)[i];
    __syncthreads();
    int warp = t >> 5, lane = t & 31;
    float sc2 = g_bnp[64 + lane], sh2 = g_bnp[96 + lane];
    int wgid = blockIdx.x * 8 + warp;
    int nw = gridDim.x * 8;
    float4 ps = make_float4(0.f, 0.f, 0.f, 0.f);
    float4 pq = make_float4(0.f, 0.f, 0.f, 0.f);
    for (int m = wgid; m < M; m += nw) {
        float cv = __ldg(&g_cv[(size_t)m * CMID + lane]);
        float y = fmaf(cv, sc2, sh2);
        y = fmaxf(y, NEG * y);
        ((float*)x2s4[warp])[lane] = y;
        __syncwarp();
        float4 acc = make_float4(0.f, 0.f, 0.f, 0.f);
        #pragma unroll
        for (int c0 = 0; c0 < 8; c0++) {
            float4 xq = x2s4[warp][c0];           // broadcast LDS.128
            float4 w0 = sw2[(4*c0 + 0) * 32 + lane];
            acc.x = fmaf(xq.x, w0.x, acc.x); acc.y = fmaf(xq.x, w0.y, acc.y);
            acc.z = fmaf(xq.x, w0.z, acc.z); acc.w = fmaf(xq.x, w0.w, acc.w);
            float4 w1 = sw2[(4*c0 + 1) * 32 + lane];
            acc.x = fmaf(xq.y, w1.x, acc.x); acc.y = fmaf(xq.y, w1.y, acc.y);
            acc.z = fmaf(xq.y, w1.z, acc.z); acc.w = fmaf(xq.y, w1.w, acc.w);
            float4 w2 = sw2[(4*c0 + 2) * 32 + lane];
            acc.x = fmaf(xq.z, w2.x, acc.x); acc.y = fmaf(xq.z, w2.y, acc.y);
            acc.z = fmaf(xq.z, w2.z, acc.z); acc.w = fmaf(xq.z, w2.w, acc.w);
            float4 w3 = sw2[(4*c0 + 3) * 32 + lane];
            acc.x = fmaf(xq.w, w3.x, acc.x); acc.y = fmaf(xq.w, w3.y, acc.y);
            acc.z = fmaf(xq.w, w3.z, acc.z); acc.w = fmaf(xq.w, w3.w, acc.w);
        }
        ((float4*)out)[(size_t)m * 32 + lane] = acc;
        ps.x += acc.x; ps.y += acc.y; ps.z += acc.z; ps.w += acc.w;
        pq.x = fmaf(acc.x, acc.x, pq.x); pq.y = fmaf(acc.y, acc.y, pq.y);
        pq.z = fmaf(acc.z, acc.z, pq.z); pq.w = fmaf(acc.w, acc.w, pq.w);
        __syncwarp();
    }
    red4[0][warp][lane] = ps;
    red4[1][warp][lane] = pq;
    __syncthreads();
    if (warp < 2) {
        float4 s = make_float4(0.f, 0.f, 0.f, 0.f);
        #pragma unroll
        for (int w = 0; w < 8; w++) {
            float4 v = red4[warp][w][lane];
            s.x += v.x; s.y += v.y; s.z += v.z; s.w += v.w;
        }
        int base = 128 + warp * 128 + 4 * lane;   // warp0 -> sums, warp1 -> squares
        atomicAdd(&g_stats[base + 0], s.x);
        atomicAdd(&g_stats[base + 1], s.y);
        atomicAdd(&g_stats[base + 2], s.z);
        atomicAdd(&g_stats[base + 3], s.w);
    }
}

// ---------- final: bn3(x3) + s_feats, lrelu (float4) ----------
__global__ void k_final(const float* __restrict__ sfeat, float* __restrict__ out, int M) {
    int t = blockIdx.x * blockDim.x + threadIdx.x;
    int n = M * 32;                 // float4 count
    if (t < n) {
        int c4 = (t & 31) * 4;
        float4 x = ((const float4*)out)[t];
        float4 s = ((const float4*)sfeat)[t];
        float4 r;
        float y;
        y = fmaf(x.x, g_bnp[128 + c4 + 0], g_bnp[256 + c4 + 0]) + s.x; r.x = fmaxf(y, NEG * y);
        y = fmaf(x.y, g_bnp[128 + c4 + 1], g_bnp[256 + c4 + 1]) + s.y; r.y = fmaxf(y, NEG * y);
        y = fmaf(x.z, g_bnp[128 + c4 + 2], g_bnp[256 + c4 + 2]) + s.z; r.z = fmaxf(y, NEG * y);
        y = fmaf(x.w, g_bnp[128 + c4 + 3], g_bnp[256 + c4 + 3]) + s.w; r.w = fmaxf(y, NEG * y);
        ((float4*)out)[t] = r;
    }
}

extern "C" void kernel_launch(void* const* d_in, const int* in_sizes, int n_in,
                              void* d_out, int out_size) {
    const float* q_pts  = (const float*)d_in[0];
    const float* s_pts  = (const float*)d_in[1];
    const float* sfeat  = (const float*)d_in[2];
    const int*   nidx   = (const int*)  d_in[3];
    const float* kp     = (const float*)d_in[4];
    const float* w_u1   = (const float*)d_in[5];
    const float* g_u1   = (const float*)d_in[6];
    const float* b_u1   = (const float*)d_in[7];
    const float* w_g1   = (const float*)d_in[8];
    const float* b_g1   = (const float*)d_in[9];
    const float* w_g2   = (const float*)d_in[10];
    const float* b_g2   = (const float*)d_in[11];
    const float* g_c    = (const float*)d_in[12];
    const float* b_c    = (const float*)d_in[13];
    const float* w_u2   = (const float*)d_in[14];
    const float* g_u2   = (const float*)d_in[15];
    const float* b_u2   = (const float*)d_in[16];
    float* out = (float*)d_out;

    int M = in_sizes[2] / CIN;
    float invM = 1.0f / (float)M;

    zero_stats<<<1, 384>>>();
    k_unary1<<<592, 256>>>(sfeat, w_u1, M);
    finalize_bn<<<1, 32>>>(0, 32, invM, g_u1, b_u1);
    k_conv<<<592, 256>>>(q_pts, s_pts, nidx, kp, w_g1, b_g1, w_g2, b_g2, M);
    finalize_bn<<<1, 32>>>(64, 32, invM, g_c, b_c);
    k_unary2<<<592, 256>>>(w_u2, out, M);
    finalize_bn<<<1, 128>>>(128, 128, invM, g_u2, b_u2);
    {
        int n = M * 32;
        k_final<<<(n + 255) / 256, 256>>>(sfeat, out, M);
    }
}